// round 17
// baseline (speedup 1.0000x reference)
#include <cuda_runtime.h>
#include <cuda_bf16.h>

// Scratch (no cudaMalloc). Shapes: B=1024 (<=4096), E=50000 (<=65536).
__device__ float g_hr[4096];        // hr_part[b] + bias
__device__ float g_tail_fb[65536];  // fallback path only

#define THREADS 256
#define ETILE   64    // e-rows per fused CTA
#define GROUPS  2     // 2 groups of 32 e-rows

// ---------------------------------------------------------------------------
// Kernel 1 (tiny): hr_part[b] = hr[b,:].W1 + bias (warp/row, batched loads)
// + trailing zero-fill. Ends with PDL trigger.
// ---------------------------------------------------------------------------
__global__ void hr_dots_kernel(const float* __restrict__ hr,
                               const float* __restrict__ W,
                               const float* __restrict__ bias,
                               int B,
                               float* __restrict__ out,
                               long long zstart, long long total) {
    int gid  = blockIdx.x * blockDim.x + threadIdx.x;
    int warp = gid >> 5;
    int lane = threadIdx.x & 31;

    long long zi = zstart + (long long)gid;
    if (zi < total) out[zi] = 0.0f;

    if (warp < B) {
        const float4* r4 = reinterpret_cast<const float4*>(hr + (size_t)warp * 512);
        const float4* w4 = reinterpret_cast<const float4*>(W);
        float4 a0 = __ldg(r4 + lane),      a1 = __ldg(r4 + lane + 32),
               a2 = __ldg(r4 + lane + 64), a3 = __ldg(r4 + lane + 96);
        float4 b0 = __ldg(w4 + lane),      b1 = __ldg(w4 + lane + 32),
               b2 = __ldg(w4 + lane + 64), b3 = __ldg(w4 + lane + 96);
        float s0 = a0.x*b0.x + a0.y*b0.y + a0.z*b0.z + a0.w*b0.w;
        float s1 = a1.x*b1.x + a1.y*b1.y + a1.z*b1.z + a1.w*b1.w;
        float s2 = a2.x*b2.x + a2.y*b2.y + a2.z*b2.z + a2.w*b2.w;
        float s3 = a3.x*b3.x + a3.y*b3.y + a3.z*b3.z + a3.w*b3.w;
        float acc = (s0 + s1) + (s2 + s3);
#pragma unroll
        for (int off = 16; off; off >>= 1)
            acc += __shfl_xor_sync(0xffffffffu, acc, off);
        if (lane == 0) g_hr[warp] = acc + bias[0];
    }
    cudaTriggerProgrammaticLaunchCompletion();
}

// ---------------------------------------------------------------------------
// Kernel 2 (fused, C==512): CTA owns 64 e-rows, 2 groups of 32.
// Pipeline: dots(0); [stores(0) issued, then dots(1) reads]; stores(1).
// Stores are non-blocking -> they drain through LTS while the next group's
// DRAM reads are outstanding: read & write streams share the pipe.
// ---------------------------------------------------------------------------
__global__ __launch_bounds__(THREADS)
void fused_v2_kernel(const float* __restrict__ tail,
                     const float* __restrict__ W2,   // W + 512
                     float* __restrict__ out,
                     int B, int E) {
    __shared__ __align__(16) float sh_t[GROUPS][32];
    __shared__ float sh_h[4096];

    const int tid = threadIdx.x;
    const int w   = tid >> 5;     // warp 0..7
    const int l   = tid & 31;
    const int e0  = blockIdx.x * ETILE;
    const int E4  = E >> 2;

    // W2 lane-slice in registers.
    const float4* w4 = reinterpret_cast<const float4*>(W2);
    float4 b0 = __ldg(w4 + l),      b1 = __ldg(w4 + l + 32),
           b2 = __ldg(w4 + l + 64), b3 = __ldg(w4 + l + 96);

    // Warp-per-4-rows dot for one 32-row group.
    auto dot_group = [&](int g) {
#pragma unroll
        for (int j = 0; j < 4; j++) {
            int rl = w * 4 + j;                // 0..31 within group
            int e  = e0 + g * 32 + rl;
            if (e < E) {
                const float4* r4 =
                    reinterpret_cast<const float4*>(tail + (size_t)e * 512);
                float4 a0 = __ldg(r4 + l),      a1 = __ldg(r4 + l + 32),
                       a2 = __ldg(r4 + l + 64), a3 = __ldg(r4 + l + 96);
                float s0 = a0.x*b0.x + a0.y*b0.y + a0.z*b0.z + a0.w*b0.w;
                float s1 = a1.x*b1.x + a1.y*b1.y + a1.z*b1.z + a1.w*b1.w;
                float s2 = a2.x*b2.x + a2.y*b2.y + a2.z*b2.z + a2.w*b2.w;
                float s3 = a3.x*b3.x + a3.y*b3.y + a3.z*b3.z + a3.w*b3.w;
                float acc = (s0 + s1) + (s2 + s3);
#pragma unroll
                for (int off = 16; off; off >>= 1)
                    acc += __shfl_xor_sync(0xffffffffu, acc, off);
                if (l == 0) sh_t[g][rl] = acc;
            }
        }
    };

    // Store one group: 8 float4 cols x B rows. Warp instruction covers
    // 4 rows x 128B = 4 full sectors (coalesced).
    const int col8 = tid & 7;
    const int brow = tid >> 3;   // 0..31
    float4* out4 = reinterpret_cast<float4*>(out);
    auto store_group = [&](int g) {
        int col4 = (e0 >> 2) + g * 8 + col8;
        if (col4 < E4) {
            float4 t = *reinterpret_cast<const float4*>(&sh_t[g][col8 * 4]);
            for (int b = brow; b < B; b += 32) {
                float h = sh_h[b];
                float4 r = make_float4(t.x + h, t.y + h, t.z + h, t.w + h);
                __stcs(out4 + (size_t)b * E4 + col4, r);
            }
        }
    };

    // ---- pipeline ----
    dot_group(0);                      // pure reads (hr kernel runs under this)
    cudaGridDependencySynchronize();   // hr results ready (long since)
    for (int b = tid; b < B; b += THREADS)
        sh_h[b] = g_hr[b];
    __syncthreads();

    store_group(0);                    // non-blocking stores issued first...
    dot_group(1);                      // ...drain while these reads wait
    __syncthreads();

    store_group(1);
}

// ---------------------------------------------------------------------------
// Generic fallback (odd shapes): dots over B+E rows, then scalar broadcast.
// ---------------------------------------------------------------------------
__global__ void dots_kernel(const float* __restrict__ hr,
                            const float* __restrict__ tail,
                            const float* __restrict__ W,
                            const float* __restrict__ bias,
                            int B, int E, int C,
                            float* __restrict__ out,
                            long long zstart, long long total) {
    int gid  = blockIdx.x * blockDim.x + threadIdx.x;
    int warp = gid >> 5;
    int lane = threadIdx.x & 31;
    long long zi = zstart + (long long)gid;
    if (zi < total) out[zi] = 0.0f;
    if (warp >= B + E) return;
    const float* row; const float* w;
    if (warp < B) { row = hr   + (size_t)warp * C;       w = W;     }
    else          { row = tail + (size_t)(warp - B) * C; w = W + C; }
    float acc = 0.0f;
    for (int k = lane; k < C; k += 32)
        acc += __ldg(row + k) * __ldg(w + k);
#pragma unroll
    for (int off = 16; off; off >>= 1)
        acc += __shfl_xor_sync(0xffffffffu, acc, off);
    if (lane == 0) {
        if (warp < B) g_hr[warp] = acc + bias[0];
        else          g_tail_fb[warp - B] = acc;
    }
}

__global__ void bcast_scalar_kernel(float* __restrict__ out, int E) {
    int e = blockIdx.x * blockDim.x + threadIdx.x;
    if (e >= E) return;
    int b = blockIdx.y;
    out[(size_t)b * E + e] = g_hr[b] + g_tail_fb[e];
}

extern "C" void kernel_launch(void* const* d_in, const int* in_sizes, int n_in,
                              void* d_out, int out_size) {
    const float* hr   = (const float*)d_in[0];  // [B, C]
    const float* tail = (const float*)d_in[1];  // [E, C]
    const float* W    = (const float*)d_in[2];  // [1, 2C]
    const float* bias = (const float*)d_in[3];  // [1]
    float* out = (float*)d_out;

    int C = in_sizes[2] / 2;
    int B = in_sizes[0] / C;
    int E = in_sizes[1] / C;

    long long BE    = (long long)B * (long long)E;
    long long total = (long long)out_size;

    bool fast = (C == 512) && ((E & 3) == 0) && (B <= 4096);

    if (fast) {
        // 1) hr dots + zero-fill (tiny), PDL-triggering
        {
            long long lanes = (long long)B * 32;
            long long extra = (total > BE) ? (total - BE) : 0;
            if (extra > lanes) lanes = extra;
            int blocks = (int)((lanes + THREADS - 1) / THREADS);
            hr_dots_kernel<<<blocks, THREADS>>>(hr, W, bias, B, out, BE, total);
        }
        // 2) fused grouped tail-dots + broadcast (PDL)
        {
            int blocks = (E + ETILE - 1) / ETILE;
            cudaLaunchConfig_t cfg = {};
            cfg.gridDim  = dim3(blocks, 1, 1);
            cfg.blockDim = dim3(THREADS, 1, 1);
            cudaLaunchAttribute attrs[1];
            attrs[0].id = cudaLaunchAttributeProgrammaticStreamSerialization;
            attrs[0].val.programmaticStreamSerializationAllowed = 1;
            cfg.attrs = attrs;
            cfg.numAttrs = 1;
            cudaLaunchKernelEx(&cfg, fused_v2_kernel, tail, W + C, out, B, E);
        }
    } else {
        {
            int rows = B + E;
            long long lanes = (long long)rows * 32;
            long long extra = (total > BE) ? (total - BE) : 0;
            if (extra > lanes) lanes = extra;
            int blocks = (int)((lanes + THREADS - 1) / THREADS);
            dots_kernel<<<blocks, THREADS>>>(hr, tail, W, bias, B, E, C,
                                             out, BE, total);
        }
        {
            dim3 grid((E + THREADS - 1) / THREADS, B);
            bcast_scalar_kernel<<<grid, THREADS>>>(out, E);
        }
    }
}